// round 1
// baseline (speedup 1.0000x reference)
#include <cuda_runtime.h>

// ---------------------------------------------------------------------------
// Flow_25108378812712
//   pos_flow = conv3d(features[16,128^3], w[3,16,3,3,3]) + bias
//   f = resize(pos_flow, 64^3) * 0.5 / 128
//   7x: f = f + warp(f, f)
//   flow = resize(f * 2, 128^3)
//   moved = warp(label, flow)
//   out = [moved (128^3) | flow (3 x 128^3)]
// ---------------------------------------------------------------------------

#define NC   16
#define DD   128
#define DHWf (128*128*128)
#define DS   64
#define DHWs (64*64*64)

// scratch (no allocation allowed; device globals)
__device__ float g_pos[3 * DHWf];   // conv output, 25 MB
__device__ float g_fa[3 * DHWs];    // ping
__device__ float g_fb[3 * DHWs];    // pong

// ---------------------------------------------------------------------------
// Trilinear sample with voxelmorph/grid_sample(zeros, align_corners) semantics:
// per-axis weight is zeroed when the corner index is out of range, index clamped.
// ---------------------------------------------------------------------------
template <int C>
__device__ __forceinline__ void sample_vol(const float* __restrict__ vol,
                                           int Dd, int Hh, int Ww,
                                           float pz, float py, float px,
                                           float* out) {
    float fz = floorf(pz), fy = floorf(py), fx = floorf(px);
    int z0 = (int)fz, y0 = (int)fy, x0 = (int)fx;
    float tz = pz - fz, ty = py - fy, tx = px - fx;

    float wz[2], wy[2], wx[2];
    int zi[2], yi[2], xi[2];

    wz[0] = ((unsigned)z0       < (unsigned)Dd) ? (1.f - tz) : 0.f;
    wz[1] = ((unsigned)(z0 + 1) < (unsigned)Dd) ? tz         : 0.f;
    zi[0] = min(max(z0, 0), Dd - 1);
    zi[1] = min(max(z0 + 1, 0), Dd - 1);

    wy[0] = ((unsigned)y0       < (unsigned)Hh) ? (1.f - ty) : 0.f;
    wy[1] = ((unsigned)(y0 + 1) < (unsigned)Hh) ? ty         : 0.f;
    yi[0] = min(max(y0, 0), Hh - 1);
    yi[1] = min(max(y0 + 1, 0), Hh - 1);

    wx[0] = ((unsigned)x0       < (unsigned)Ww) ? (1.f - tx) : 0.f;
    wx[1] = ((unsigned)(x0 + 1) < (unsigned)Ww) ? tx         : 0.f;
    xi[0] = min(max(x0, 0), Ww - 1);
    xi[1] = min(max(x0 + 1, 0), Ww - 1);

    const int cs = Dd * Hh * Ww;
    float acc[C];
#pragma unroll
    for (int c = 0; c < C; c++) acc[c] = 0.f;

#pragma unroll
    for (int a = 0; a < 2; a++) {
#pragma unroll
        for (int b = 0; b < 2; b++) {
#pragma unroll
            for (int e = 0; e < 2; e++) {
                float w = wz[a] * wy[b] * wx[e];
                int off = (zi[a] * Hh + yi[b]) * Ww + xi[e];
#pragma unroll
                for (int c = 0; c < C; c++)
                    acc[c] += w * __ldg(vol + c * cs + off);
            }
        }
    }
#pragma unroll
    for (int c = 0; c < C; c++) out[c] = acc[c];
}

// ---------------------------------------------------------------------------
// Conv3d 16->3, 3x3x3, pad 1. Block = 128 threads (32 x-quads, 4 z-rows) for a
// (4z, 1y, 128x) tile. Per-channel smem slab (6z, 3y, 130x) + full weights in
// smem. Each thread accumulates 3oc x 4x in registers -> 5184 FMA/thread,
// FMA-pipe bound.
// ---------------------------------------------------------------------------
__global__ void __launch_bounds__(128, 8)
conv3d_kernel(const float* __restrict__ feat,
              const float* __restrict__ wgt,
              const float* __restrict__ bias) {
    __shared__ float s_w[3 * NC * 27];   // 1296
    __shared__ float s_in[6][3][130];

    const int tx  = threadIdx.x;              // 0..31  (x quad)
    const int tz  = threadIdx.y;              // 0..3   (z within tile)
    const int tid = tz * 32 + tx;
    const int y   = blockIdx.x;               // 0..127
    const int z0  = blockIdx.y * 4;           // 0..124

    for (int i = tid; i < 3 * NC * 27; i += 128) s_w[i] = wgt[i];

    float acc[3][4];
#pragma unroll
    for (int oc = 0; oc < 3; oc++) {
        float b = __ldg(bias + oc);
#pragma unroll
        for (int q = 0; q < 4; q++) acc[oc][q] = b;
    }

    for (int c = 0; c < NC; c++) {
        __syncthreads();   // also makes s_w visible on first iter
        // fill slab for channel c: rows z0-1..z0+4, y-1..y+1, x -1..128
        for (int i = tid; i < 6 * 3 * 130; i += 128) {
            int zz = i / 390;
            int r  = i - zz * 390;
            int yy = r / 130;
            int xx = r - yy * 130;
            int gz = z0 - 1 + zz;
            int gy = y - 1 + yy;
            int gx = xx - 1;
            float v = 0.f;
            if ((unsigned)gz < (unsigned)DD && (unsigned)gy < (unsigned)DD &&
                (unsigned)gx < (unsigned)DD)
                v = __ldg(feat + ((c * DD + gz) * DD + gy) * DD + gx);
            s_in[zz][yy][xx] = v;
        }
        __syncthreads();

#pragma unroll
        for (int ky = 0; ky < 3; ky++) {
#pragma unroll
            for (int kz = 0; kz < 3; kz++) {
                float v[6];
#pragma unroll
                for (int q = 0; q < 6; q++) v[q] = s_in[tz + kz][ky][4 * tx + q];
#pragma unroll
                for (int kx = 0; kx < 3; kx++) {
                    int wi = c * 27 + kz * 9 + ky * 3 + kx;
                    float w0 = s_w[wi];
                    float w1 = s_w[432 + wi];
                    float w2 = s_w[864 + wi];
#pragma unroll
                    for (int q = 0; q < 4; q++) {
                        float vv = v[kx + q];
                        acc[0][q] += w0 * vv;
                        acc[1][q] += w1 * vv;
                        acc[2][q] += w2 * vv;
                    }
                }
            }
        }
    }

    const int z    = z0 + tz;
    const int base = (z * DD + y) * DD + 4 * tx;
#pragma unroll
    for (int oc = 0; oc < 3; oc++)
#pragma unroll
        for (int q = 0; q < 4; q++)
            g_pos[oc * DHWf + base + q] = acc[oc][q];
}

// ---------------------------------------------------------------------------
// f0 = resize(pos_flow, 64^3) * (1/2) * (1/2^7)   (ResizeTransform + VecInt pre-scale)
// ---------------------------------------------------------------------------
__global__ void resize_down_kernel() {
    int idx = blockIdx.x * blockDim.x + threadIdx.x;
    if (idx >= DHWs) return;
    int k = idx & 63, j = (idx >> 6) & 63, i = idx >> 12;
    const float S = 127.f / 63.f;
    float o[3];
    sample_vol<3>(g_pos, DD, DD, DD, i * S, j * S, k * S, o);
    const float sc = 1.f / 256.f;
    g_fa[idx]            = o[0] * sc;
    g_fa[DHWs + idx]     = o[1] * sc;
    g_fa[2 * DHWs + idx] = o[2] * sc;
}

// ---------------------------------------------------------------------------
// one scaling-and-squaring step: dst = f + warp(f, f)
// ---------------------------------------------------------------------------
__global__ void vecint_kernel(int it) {
    const float* __restrict__ src = (it & 1) ? g_fb : g_fa;
    float*       __restrict__ dst = (it & 1) ? g_fa : g_fb;
    int idx = blockIdx.x * blockDim.x + threadIdx.x;
    if (idx >= DHWs) return;
    int k = idx & 63, j = (idx >> 6) & 63, i = idx >> 12;
    float fz = src[idx];
    float fy = src[DHWs + idx];
    float fx = src[2 * DHWs + idx];
    float o[3];
    sample_vol<3>(src, DS, DS, DS, i + fz, j + fy, k + fx, o);
    dst[idx]            = fz + o[0];
    dst[DHWs + idx]     = fy + o[1];
    dst[2 * DHWs + idx] = fx + o[2];
}

// ---------------------------------------------------------------------------
// flow = resize(f * 2, 128^3); moved = warp(label, flow).
// After 7 iterations (0..6), the result lives in g_fb.
// out layout: [moved | flow_z | flow_y | flow_x]
// ---------------------------------------------------------------------------
__global__ void upsample_warp_kernel(const float* __restrict__ label,
                                     float* __restrict__ out) {
    int idx = blockIdx.x * blockDim.x + threadIdx.x;
    if (idx >= DHWf) return;
    int x = idx & 127, y = (idx >> 7) & 127, z = idx >> 14;
    const float S = 63.f / 127.f;
    float fl[3];
    sample_vol<3>(g_fb, DS, DS, DS, z * S, y * S, x * S, fl);
    float flz = 2.f * fl[0];
    float fly = 2.f * fl[1];
    float flx = 2.f * fl[2];
    out[DHWf + idx]     = flz;
    out[2 * DHWf + idx] = fly;
    out[3 * DHWf + idx] = flx;
    float mv[1];
    sample_vol<1>(label, DD, DD, DD, z + flz, y + fly, x + flx, mv);
    out[idx] = mv[0];
}

// ---------------------------------------------------------------------------
extern "C" void kernel_launch(void* const* d_in, const int* in_sizes, int n_in,
                              void* d_out, int out_size) {
    const float* feat  = (const float*)d_in[0];  // [16,128,128,128]
    const float* label = (const float*)d_in[1];  // [1,128,128,128]
    const float* wgt   = (const float*)d_in[2];  // [3,16,3,3,3]
    const float* bias  = (const float*)d_in[3];  // [3]
    float* out = (float*)d_out;                  // 4*128^3

    conv3d_kernel<<<dim3(DD, DD / 4), dim3(32, 4)>>>(feat, wgt, bias);
    resize_down_kernel<<<DHWs / 256, 256>>>();
    for (int it = 0; it < 7; it++)
        vecint_kernel<<<DHWs / 256, 256>>>(it);
    upsample_warp_kernel<<<DHWf / 256, 256>>>(label, out);
}

// round 2
// speedup vs baseline: 1.7523x; 1.7523x over previous
#include <cuda_runtime.h>

// ---------------------------------------------------------------------------
// Flow_25108378812712
//   pos_flow = conv3d(features[16,128^3], w[3,16,3,3,3]) + bias
//   f = resize(pos_flow, 64^3) * 0.5 / 128
//   7x: f = f + warp(f, f)
//   flow = resize(f * 2, 128^3);  moved = warp(label, flow)
//   out = [moved | flow_z | flow_y | flow_x]
// ---------------------------------------------------------------------------

#define NC   16
#define DD   128
#define DHWf (128*128*128)
#define DS   64
#define DHWs (64*64*64)

typedef unsigned long long ull;

// scratch (device globals; allocation is forbidden)
__device__ float4 g_pos4[DHWf];   // conv output, interleaved (fz,fy,fx,0), 33.5 MB
__device__ float4 g_fa[DHWs];     // ping, 4.2 MB
__device__ float4 g_fb[DHWs];     // pong

// ---------------- packed f32x2 helpers --------------------------------------
__device__ __forceinline__ ull pack2(float lo, float hi) {
    ull r; asm("mov.b64 %0, {%1, %2};" : "=l"(r) : "f"(lo), "f"(hi)); return r;
}
__device__ __forceinline__ void unpack2(ull v, float& lo, float& hi) {
    asm("mov.b64 {%0, %1}, %2;" : "=f"(lo), "=f"(hi) : "l"(v));
}
__device__ __forceinline__ void ffma2(ull& d, ull a, ull b) {
    asm("fma.rn.f32x2 %0, %1, %2, %0;" : "+l"(d) : "l"(a), "l"(b));
}

// ---------------------------------------------------------------------------
// Trilinear sample of an interleaved float4 flow volume (cube of side D).
// grid_sample(zeros, align_corners) semantics: per-axis weight zeroed when the
// corner index is out of range, index clamped.
// ---------------------------------------------------------------------------
__device__ __forceinline__ float3 sample_flow(const float4* __restrict__ vol,
                                              int D, float pz, float py, float px) {
    float fz = floorf(pz), fy = floorf(py), fx = floorf(px);
    int z0 = (int)fz, y0 = (int)fy, x0 = (int)fx;
    float tz = pz - fz, ty = py - fy, tx = px - fx;

    float wz[2], wy[2], wx[2];
    int zi[2], yi[2], xi[2];
    wz[0] = ((unsigned)z0       < (unsigned)D) ? (1.f - tz) : 0.f;
    wz[1] = ((unsigned)(z0 + 1) < (unsigned)D) ? tz         : 0.f;
    zi[0] = min(max(z0, 0), D - 1);  zi[1] = min(max(z0 + 1, 0), D - 1);
    wy[0] = ((unsigned)y0       < (unsigned)D) ? (1.f - ty) : 0.f;
    wy[1] = ((unsigned)(y0 + 1) < (unsigned)D) ? ty         : 0.f;
    yi[0] = min(max(y0, 0), D - 1);  yi[1] = min(max(y0 + 1, 0), D - 1);
    wx[0] = ((unsigned)x0       < (unsigned)D) ? (1.f - tx) : 0.f;
    wx[1] = ((unsigned)(x0 + 1) < (unsigned)D) ? tx         : 0.f;
    xi[0] = min(max(x0, 0), D - 1);  xi[1] = min(max(x0 + 1, 0), D - 1);

    float az = 0.f, ay = 0.f, ax = 0.f;
#pragma unroll
    for (int a = 0; a < 2; a++)
#pragma unroll
        for (int b = 0; b < 2; b++)
#pragma unroll
            for (int e = 0; e < 2; e++) {
                float w = wz[a] * wy[b] * wx[e];
                float4 v = __ldg(vol + (zi[a] * D + yi[b]) * D + xi[e]);
                az += w * v.x;  ay += w * v.y;  ax += w * v.z;
            }
    return make_float3(az, ay, ax);
}

// scalar volume (label) sampler, same semantics
__device__ __forceinline__ float sample_scalar(const float* __restrict__ vol,
                                               int D, float pz, float py, float px) {
    float fz = floorf(pz), fy = floorf(py), fx = floorf(px);
    int z0 = (int)fz, y0 = (int)fy, x0 = (int)fx;
    float tz = pz - fz, ty = py - fy, tx = px - fx;
    float wz[2], wy[2], wx[2];
    int zi[2], yi[2], xi[2];
    wz[0] = ((unsigned)z0       < (unsigned)D) ? (1.f - tz) : 0.f;
    wz[1] = ((unsigned)(z0 + 1) < (unsigned)D) ? tz         : 0.f;
    zi[0] = min(max(z0, 0), D - 1);  zi[1] = min(max(z0 + 1, 0), D - 1);
    wy[0] = ((unsigned)y0       < (unsigned)D) ? (1.f - ty) : 0.f;
    wy[1] = ((unsigned)(y0 + 1) < (unsigned)D) ? ty         : 0.f;
    yi[0] = min(max(y0, 0), D - 1);  yi[1] = min(max(y0 + 1, 0), D - 1);
    wx[0] = ((unsigned)x0       < (unsigned)D) ? (1.f - tx) : 0.f;
    wx[1] = ((unsigned)(x0 + 1) < (unsigned)D) ? tx         : 0.f;
    xi[0] = min(max(x0, 0), D - 1);  xi[1] = min(max(x0 + 1, 0), D - 1);
    float acc = 0.f;
#pragma unroll
    for (int a = 0; a < 2; a++)
#pragma unroll
        for (int b = 0; b < 2; b++)
#pragma unroll
            for (int e = 0; e < 2; e++) {
                float w = wz[a] * wy[b] * wx[e];
                acc += w * __ldg(vol + (zi[a] * D + yi[b]) * D + xi[e]);
            }
    return acc;
}

// ---------------------------------------------------------------------------
// Conv3d 16->3, 3x3x3, pad 1.  Tile = (4z, 2y, 128x), block = 256 threads
// (32 x-quads x 8 zy).  Per-channel smem slab 6z x 4y x 132x; weights pre-
// packed (w,w) in smem for fma.rn.f32x2.  Each thread owns 3oc x 4x voxels
// held as 6 packed f32x2 accumulators -> 162 FFMA2 + ~99 LDS per channel.
// Split over z into 8 launches (profiling visibility; merged later).
// ---------------------------------------------------------------------------
__global__ void __launch_bounds__(256, 4)
conv3d_kernel(const float* __restrict__ feat,
              const float* __restrict__ wgt,
              const float* __restrict__ bias,
              int z_base) {
    __shared__ ull   s_w2[3 * NC * 27];      // 1296 packed weights (10.1 KB)
    __shared__ float s_in[24 * 132];         // 6z x 4y rows of 132 (12.4 KB)

    const int tx  = threadIdx.x;             // 0..31
    const int tg  = threadIdx.y;             // 0..7
    const int tid = tg * 32 + tx;
    const int tz  = tg >> 1;                 // 0..3
    const int tyy = tg & 1;                  // 0..1
    const int y0  = blockIdx.x * 2;
    const int z0  = z_base + blockIdx.y * 4;

    for (int i = tid; i < 3 * NC * 27; i += 256) {
        float w = __ldg(wgt + i);
        s_w2[i] = pack2(w, w);
    }

    // ---- fill precompute: fixed column per thread, 12 rows stride 2 ----
    const int r0 = tid >> 7;                 // 0 or 1
    const int c0 = tid & 127;                // slab column
    const int gx = c0 - 1;
    const bool xok = (unsigned)gx < 128u;
    int  off[12];
    int  vmask = 0;
#pragma unroll
    for (int k = 0; k < 12; k++) {
        int r  = r0 + 2 * k;
        int zz = r >> 2, yy = r & 3;
        int gz = z0 - 1 + zz, gy = y0 - 1 + yy;
        if (xok && (unsigned)gz < 128u && (unsigned)gy < 128u) vmask |= (1 << k);
        off[k] = (gz * 128 + gy) * 128 + gx;
    }
    // extra columns 128,129 handled by first 48 threads
    const bool ex = tid < 48;
    int exoff = 0, exsmem = 0; bool exvld = false;
    if (ex) {
        int r = tid >> 1;
        int colx = 128 + (tid & 1);
        int gx2 = colx - 1;                  // 127 or 128
        int zz = r >> 2, yy = r & 3;
        int gz = z0 - 1 + zz, gy = y0 - 1 + yy;
        exvld = (gx2 < 128) && (unsigned)gz < 128u && (unsigned)gy < 128u;
        exoff = (gz * 128 + gy) * 128 + gx2;
        exsmem = r * 132 + colx;
    }

    ull acc[3][2];
#pragma unroll
    for (int o = 0; o < 3; o++) {
        float b = __ldg(bias + o);
        acc[o][0] = pack2(b, b);
        acc[o][1] = pack2(b, b);
    }

    const float* fc = feat;
    for (int c = 0; c < NC; c++, fc += DHWf) {
        __syncthreads();
#pragma unroll
        for (int k = 0; k < 12; k++) {
            float v = (vmask & (1 << k)) ? __ldg(fc + off[k]) : 0.f;
            s_in[(r0 + 2 * k) * 132 + c0] = v;
        }
        if (ex) s_in[exsmem] = exvld ? __ldg(fc + exoff) : 0.f;
        __syncthreads();

        const ull* wrow = s_w2 + c * 27;
#pragma unroll
        for (int kz = 0; kz < 3; kz++) {
#pragma unroll
            for (int ky = 0; ky < 3; ky++) {
                const float* rp = &s_in[((tz + kz) * 4 + (tyy + ky)) * 132 + 4 * tx];
                float4 v03 = *reinterpret_cast<const float4*>(rp);
                float2 v45 = *reinterpret_cast<const float2*>(rp + 4);
                ull pl[5];
                pl[0] = pack2(v03.x, v03.y);
                pl[1] = pack2(v03.y, v03.z);
                pl[2] = pack2(v03.z, v03.w);
                pl[3] = pack2(v03.w, v45.x);
                pl[4] = pack2(v45.x, v45.y);
#pragma unroll
                for (int kx = 0; kx < 3; kx++) {
                    int t = kz * 9 + ky * 3 + kx;
                    ull w0 = wrow[t];
                    ull w1 = wrow[432 + t];
                    ull w2 = wrow[864 + t];
                    ffma2(acc[0][0], pl[kx], w0);  ffma2(acc[0][1], pl[kx + 2], w0);
                    ffma2(acc[1][0], pl[kx], w1);  ffma2(acc[1][1], pl[kx + 2], w1);
                    ffma2(acc[2][0], pl[kx], w2);  ffma2(acc[2][1], pl[kx + 2], w2);
                }
            }
        }
    }

    float a[3][4];
#pragma unroll
    for (int o = 0; o < 3; o++) {
        unpack2(acc[o][0], a[o][0], a[o][1]);
        unpack2(acc[o][1], a[o][2], a[o][3]);
    }
    const int z = z0 + tz, yv = y0 + tyy;
    const int base = (z * 128 + yv) * 128 + 4 * tx;
#pragma unroll
    for (int q = 0; q < 4; q++)
        g_pos4[base + q] = make_float4(a[0][q], a[1][q], a[2][q], 0.f);
}

// ---------------------------------------------------------------------------
// f0 = resize(pos_flow, 64^3) * (1/2) * (1/2^7)
// ---------------------------------------------------------------------------
__global__ void resize_down_kernel() {
    int idx = blockIdx.x * blockDim.x + threadIdx.x;
    if (idx >= DHWs) return;
    int k = idx & 63, j = (idx >> 6) & 63, i = idx >> 12;
    const float S = 127.f / 63.f;
    float3 o = sample_flow(g_pos4, DD, i * S, j * S, k * S);
    const float sc = 1.f / 256.f;
    g_fa[idx] = make_float4(o.x * sc, o.y * sc, o.z * sc, 0.f);
}

// ---------------------------------------------------------------------------
// one scaling-and-squaring step: dst = f + warp(f, f)
// ---------------------------------------------------------------------------
__global__ void vecint_kernel(int it) {
    const float4* __restrict__ src = (it & 1) ? g_fb : g_fa;
    float4*       __restrict__ dst = (it & 1) ? g_fa : g_fb;
    int idx = blockIdx.x * blockDim.x + threadIdx.x;
    if (idx >= DHWs) return;
    int k = idx & 63, j = (idx >> 6) & 63, i = idx >> 12;
    float4 f = __ldg(src + idx);
    float3 o = sample_flow(src, DS, i + f.x, j + f.y, k + f.z);
    dst[idx] = make_float4(f.x + o.x, f.y + o.y, f.z + o.z, 0.f);
}

// ---------------------------------------------------------------------------
// flow = resize(f * 2, 128^3); moved = warp(label, flow)
// after 7 iterations result is in g_fb.  out = [moved | fz | fy | fx]
// ---------------------------------------------------------------------------
__global__ void upsample_warp_kernel(const float* __restrict__ label,
                                     float* __restrict__ out) {
    int idx = blockIdx.x * blockDim.x + threadIdx.x;
    if (idx >= DHWf) return;
    int x = idx & 127, y = (idx >> 7) & 127, z = idx >> 14;
    const float S = 63.f / 127.f;
    float3 fl = sample_flow(g_fb, DS, z * S, y * S, x * S);
    float flz = 2.f * fl.x, fly = 2.f * fl.y, flx = 2.f * fl.z;
    out[DHWf + idx]     = flz;
    out[2 * DHWf + idx] = fly;
    out[3 * DHWf + idx] = flx;
    out[idx] = sample_scalar(label, DD, z + flz, y + fly, x + flx);
}

// ---------------------------------------------------------------------------
extern "C" void kernel_launch(void* const* d_in, const int* in_sizes, int n_in,
                              void* d_out, int out_size) {
    const float* feat  = (const float*)d_in[0];  // [16,128,128,128]
    const float* label = (const float*)d_in[1];  // [1,128,128,128]
    const float* wgt   = (const float*)d_in[2];  // [3,16,3,3,3]
    const float* bias  = (const float*)d_in[3];  // [3]
    float* out = (float*)d_out;                  // 4*128^3

    // conv split into 8 z-chunks so the ncu window (-s 5 -c 1, launch #6)
    // lands on a conv chunk
    for (int zc = 0; zc < 8; zc++)
        conv3d_kernel<<<dim3(64, 4), dim3(32, 8)>>>(feat, wgt, bias, zc * 16);
    resize_down_kernel<<<DHWs / 256, 256>>>();
    for (int it = 0; it < 7; it++)
        vecint_kernel<<<DHWs / 256, 256>>>(it);
    upsample_warp_kernel<<<DHWf / 256, 256>>>(label, out);
}